// round 17
// baseline (speedup 1.0000x reference)
#include <cuda_runtime.h>
#include <cuda_bf16.h>
#include <math.h>
#include <stdint.h>

// Problem constants (fixed by setup_inputs)
#define NR 6144          // rows
#define KB 128           // BIT
#define NC 200           // classes
#define NBK 2048         // histogram buckets, width 1/32 over [-32,32)
#define TPB 256

#define UBF 64.0f
#define CCOEF (-0.28719499063341186f)   // (1/16)*ln(1/99)
#define ACOEF 2.0f
#define ALPHAF 0.1f

typedef unsigned long long u64;

// ---------------- device scratch (no cudaMalloc allowed) ----------------
static __device__ __nv_bfloat16 g_hi[(size_t)NR * KB];
static __device__ __nv_bfloat16 g_lo[(size_t)NR * KB];
static __device__ float g_inner[(size_t)NR * NR];      // ~151 MB
static __device__ int   g_lab[NR];
static __device__ float g_rowPos[NR];
static __device__ float g_rowNeg[NR];
static __device__ float g_rowQ[NR];
static __device__ int   g_valid[NR];
static __device__ int   g_bad;                         // GEMM verification flag

// ---------------- mma.sync helpers (sm_80+ PTX; legal on compute_103) ----------------
__device__ __forceinline__ uint32_t smem_u32(const void* p) {
    uint32_t a;
    asm("{ .reg .u64 t; cvta.to.shared.u64 t, %1; cvt.u32.u64 %0, t; }" : "=r"(a) : "l"(p));
    return a;
}
__device__ __forceinline__ void ldmx4(uint32_t* r, uint32_t addr) {
    asm volatile("ldmatrix.sync.aligned.m8n8.x4.shared.b16 {%0,%1,%2,%3}, [%4];"
                 : "=r"(r[0]), "=r"(r[1]), "=r"(r[2]), "=r"(r[3]) : "r"(addr));
}
__device__ __forceinline__ void ldmx2(uint32_t* r, uint32_t addr) {
    asm volatile("ldmatrix.sync.aligned.m8n8.x2.shared.b16 {%0,%1}, [%2];"
                 : "=r"(r[0]), "=r"(r[1]) : "r"(addr));
}
__device__ __forceinline__ void mma16816(float* c, const uint32_t* a, const uint32_t* b) {
    asm volatile("mma.sync.aligned.m16n8k16.row.col.f32.bf16.bf16.f32 "
                 "{%0,%1,%2,%3}, {%4,%5,%6,%7}, {%8,%9}, {%0,%1,%2,%3};"
                 : "+f"(c[0]), "+f"(c[1]), "+f"(c[2]), "+f"(c[3])
                 : "r"(a[0]), "r"(a[1]), "r"(a[2]), "r"(a[3]), "r"(b[0]), "r"(b[1]));
}

// packed fp32x2 FMA (fallback GEMM)
__device__ __forceinline__ u64 ffma2(u64 a, u64 b, u64 c) {
    u64 d;
    asm("fma.rn.f32x2 %0, %1, %2, %3;" : "=l"(d) : "l"(a), "l"(b), "l"(c));
    return d;
}
__device__ __forceinline__ u64 packf2(float lo, float hi) {
    return ((u64)__float_as_uint(hi) << 32) | (u64)__float_as_uint(lo);
}

// ---------------- helpers ----------------
__device__ __forceinline__ float block_reduce_f(float v, float* buf) {
    int t = threadIdx.x;
    __syncthreads();
    buf[t] = v;
    __syncthreads();
    for (int s = TPB / 2; s > 0; s >>= 1) {
        if (t < s) buf[t] += buf[t + s];
        __syncthreads();
    }
    return buf[0];
}
__device__ __forceinline__ int block_reduce_i(int v, int* buf) {
    int t = threadIdx.x;
    __syncthreads();
    buf[t] = v;
    __syncthreads();
    for (int s = TPB / 2; s > 0; s >>= 1) {
        if (t < s) buf[t] += buf[t + s];
        __syncthreads();
    }
    return buf[0];
}
__device__ __forceinline__ float softplus_f(float x) {
    return fmaxf(x, 0.0f) + log1pf(expf(-fabsf(x)));
}
__device__ __forceinline__ int bucket_of(float v) {
    int b = (int)floorf((v + 32.0f) * 32.0f);
    return min(max(b, 0), NBK - 1);
}

// ---------------- 1) tanh + bf16 split + labels + quantization ----------------
__global__ void prep_kernel(const float* __restrict__ u, const int* __restrict__ y) {
    int row = blockIdx.x;
    int t = threadIdx.x;   // 128 threads
    if (row == 0 && t == 0) g_bad = 0;   // reset verification flag every launch
    float uh = tanhf(u[row * KB + t]);
    __nv_bfloat16 hi = __float2bfloat16_rn(uh);
    float hif = __bfloat162float(hi);
    __nv_bfloat16 lo = __float2bfloat16_rn(uh - hif);
    g_hi[(size_t)row * KB + t] = hi;
    g_lo[(size_t)row * KB + t] = lo;
    float sg = (uh > 0.0f) ? 1.0f : ((uh < 0.0f) ? -1.0f : 0.0f);
    float d = uh - sg;
    float q = d * d;
    for (int j = t; j < NC; j += KB)
        if (y[row * NC + j] == 1) g_lab[row] = j;
    __shared__ float buf[KB];
    buf[t] = q;
    __syncthreads();
    for (int s = KB / 2; s > 0; s >>= 1) {
        if (t < s) buf[t] += buf[t + s];
        __syncthreads();
    }
    if (t == 0) g_rowQ[row] = buf[0];
}

// ---------------- 2) HMMA GEMM: inner = hi*hi^T + hi*lo^T + lo*hi^T ----------------
// 128x128 output tile per CTA (upper triangle), 256 threads (8 warps, warp tile 64x32).
// smem tiles padded to 272B row stride (ldmatrix conflict-free: 272/4 % 32 = 4).
#define GT 128
#define ROWB 272                 // bytes per padded smem row (128 bf16 + 8 pad)
#define TILE_B (GT * ROWB)       // 34816 bytes per tile
#define AT_HI 0
#define AT_LO (1 * TILE_B)
#define BT_HI (2 * TILE_B)
#define BT_LO (3 * TILE_B)
#define MMA_SMEM (4 * TILE_B)    // 139264 bytes

__global__ void __launch_bounds__(256, 1) gemm_mma_kernel() {
    int bx = blockIdx.x;   // col tile
    int by = blockIdx.y;   // row tile
    if (bx < by) return;

    extern __shared__ __align__(16) char sm[];
    uint32_t smaddr = smem_u32(sm);

    int tid = threadIdx.x;
    int wid = tid >> 5;
    int lane = tid & 31;
    int rowBase = by * GT, colBase = bx * GT;

    // load 4 tiles: Ahi, Alo (rows rowBase..), Bhi, Blo (rows colBase..)
    const uint4* hsrc = (const uint4*)g_hi;
    const uint4* lsrc = (const uint4*)g_lo;
#pragma unroll
    for (int t4 = 0; t4 < 4; t4++) {
        int isB = t4 >> 1;
        int isLo = t4 & 1;
        int baseRow = isB ? colBase : rowBase;
        const uint4* src = isLo ? lsrc : hsrc;
        char* dst = sm + t4 * TILE_B;
#pragma unroll
        for (int it = 0; it < 8; it++) {
            int idx = tid + it * 256;          // 0..2047
            int r = idx >> 4;                  // 0..127
            int c = idx & 15;                  // 16B chunk in row
            uint4 v = src[(size_t)(baseRow + r) * (KB / 8) + c];
            *(uint4*)(dst + r * ROWB + c * 16) = v;
        }
    }
    __syncthreads();

    int warpM = wid >> 2, warpN = wid & 3;
    int m0w = warpM * 64, n0w = warpN * 32;

    // canonical ldmatrix per-lane address offsets
    int a_row = ((lane >> 3) & 1) * 8 + (lane & 7);   // x4: mats [r0-7,k0][r8-15,k0][r0-7,k8][r8-15,k8]
    int a_col = (lane >> 4) * 8;
    int b_row = lane & 7;                              // x2: mats [n0-7,k0][n0-7,k8]
    int b_col = ((lane >> 3) & 1) * 8;

    float acc[4][4][4];
#pragma unroll
    for (int ma = 0; ma < 4; ma++)
#pragma unroll
        for (int na = 0; na < 4; na++)
#pragma unroll
            for (int e = 0; e < 4; e++) acc[ma][na][e] = 0.0f;

#pragma unroll 2
    for (int ks = 0; ks < 8; ks++) {
        int k0 = ks * 16;
        uint32_t ahi[4][4], alo[4][4];
#pragma unroll
        for (int ma = 0; ma < 4; ma++) {
            uint32_t roff = (uint32_t)((m0w + ma * 16 + a_row) * ROWB + (k0 + a_col) * 2);
            ldmx4(ahi[ma], smaddr + AT_HI + roff);
            ldmx4(alo[ma], smaddr + AT_LO + roff);
        }
        uint32_t bhi[4][2], blo[4][2];
#pragma unroll
        for (int na = 0; na < 4; na++) {
            uint32_t boff = (uint32_t)((n0w + na * 8 + b_row) * ROWB + (k0 + b_col) * 2);
            ldmx2(bhi[na], smaddr + BT_HI + boff);
            ldmx2(blo[na], smaddr + BT_LO + boff);
        }
#pragma unroll
        for (int ma = 0; ma < 4; ma++)
#pragma unroll
            for (int na = 0; na < 4; na++) {
                mma16816(acc[ma][na], ahi[ma], bhi[na]);
                mma16816(acc[ma][na], ahi[ma], blo[na]);
                mma16816(acc[ma][na], alo[ma], bhi[na]);
            }
    }
    __syncthreads();   // operands dead; alias stage over operand smem

    // stage: acc -> smem [128][132]
    float (*stage)[132] = (float (*)[132])sm;
    {
        int rq = lane >> 2;           // 0..7
        int cq = (lane & 3) * 2;      // 0,2,4,6
#pragma unroll
        for (int ma = 0; ma < 4; ma++)
#pragma unroll
            for (int na = 0; na < 4; na++) {
                int r0 = m0w + ma * 16 + rq;
                int c0 = n0w + na * 8 + cq;
                stage[r0][c0 + 0] = acc[ma][na][0];
                stage[r0][c0 + 1] = acc[ma][na][1];
                stage[r0 + 8][c0 + 0] = acc[ma][na][2];
                stage[r0 + 8][c0 + 1] = acc[ma][na][3];
            }
    }
    __syncthreads();

    // upper tile store (coalesced)
    for (int idx = tid; idx < GT * GT / 4; idx += 256) {
        int r = idx >> 5;
        int c4 = idx & 31;
        float4 v = *(const float4*)&stage[r][c4 * 4];
        *(float4*)&g_inner[(size_t)(rowBase + r) * NR + colBase + c4 * 4] = v;
    }
    // mirror (off-diagonal): transposed read from stage, coalesced store
    if (bx != by) {
        for (int idx = tid; idx < GT * GT / 4; idx += 256) {
            int rr = idx >> 5;
            int c4 = idx & 31;
            float4 v;
            v.x = stage[c4 * 4 + 0][rr];
            v.y = stage[c4 * 4 + 1][rr];
            v.z = stage[c4 * 4 + 2][rr];
            v.w = stage[c4 * 4 + 3][rr];
            *(float4*)&g_inner[(size_t)(colBase + rr) * NR + rowBase + c4 * 4] = v;
        }
    }
}

// ---------------- 2b) verify sampled entries of g_inner against scalar recompute ----------------
__global__ void __launch_bounds__(256) verify_kernel() {
    int t = threadIdx.x;   // single block, 256 threads
    for (int s = 0; s < 4; s++) {
        int idx = t * 4 + s;                       // 0..1023 samples
        int i = (1009 * idx + 13) % NR;
        int j = (2003 * idx + 57) % NR;
        float acc = 0.0f;
        for (int k = 0; k < KB; k++) {
            float hi_i = __bfloat162float(g_hi[(size_t)i * KB + k]);
            float lo_i = __bfloat162float(g_lo[(size_t)i * KB + k]);
            float hi_j = __bfloat162float(g_hi[(size_t)j * KB + k]);
            float lo_j = __bfloat162float(g_lo[(size_t)j * KB + k]);
            acc += hi_i * hi_j + hi_i * lo_j + lo_i * hi_j;
        }
        float got = g_inner[(size_t)i * NR + j];
        if (fabsf(got - acc) > 0.05f + 1e-3f * fabsf(acc))
            atomicExch(&g_bad, 1);
    }
}

// ---------------- 2c) guarded fallback GEMM (R2-validated FFMA2 path) ----------------
#define PADU 70
__global__ void __launch_bounds__(256) gemm_fb_kernel() {
    if (g_bad == 0) return;        // HMMA GEMM verified good -> nothing to do
    int bx = blockIdx.x, by = blockIdx.y;
    if (bx < by) return;

    __shared__ __align__(16) char smraw[2 * 16 * PADU * 8];
    u64 (*As)[PADU] = (u64 (*)[PADU])smraw;
    u64 (*Bs)[PADU] = (u64 (*)[PADU])(smraw + 16 * PADU * 8);

    int tid = threadIdx.x;
    int tx = tid & 15, ty = tid >> 4;
    int rowBase = by * 64, colBase = bx * 64;

    u64 acc[4][4];
#pragma unroll
    for (int i = 0; i < 4; i++)
#pragma unroll
        for (int j = 0; j < 4; j++) acc[i][j] = 0ull;

    for (int kc = 0; kc < 4; kc++) {
#pragma unroll
        for (int l = 0; l < 2; l++) {
            int idx = tid + l * 256;
            int r = idx >> 3;
            int q = idx & 7;
            size_t offA = (size_t)(rowBase + r) * KB + kc * 32 + q * 4;
            const __nv_bfloat162* hA = (const __nv_bfloat162*)&g_hi[offA];
            const __nv_bfloat162* lA = (const __nv_bfloat162*)&g_lo[offA];
            __nv_bfloat162 h0 = hA[0], h1 = hA[1], l0 = lA[0], l1 = lA[1];
            float a0 = __bfloat162float(h0.x) + __bfloat162float(l0.x);
            float a1 = __bfloat162float(h0.y) + __bfloat162float(l0.y);
            float a2 = __bfloat162float(h1.x) + __bfloat162float(l1.x);
            float a3 = __bfloat162float(h1.y) + __bfloat162float(l1.y);
            As[q * 2 + 0][r] = packf2(a0, a1);
            As[q * 2 + 1][r] = packf2(a2, a3);
            size_t offB = (size_t)(colBase + r) * KB + kc * 32 + q * 4;
            const __nv_bfloat162* hB = (const __nv_bfloat162*)&g_hi[offB];
            const __nv_bfloat162* lB = (const __nv_bfloat162*)&g_lo[offB];
            __nv_bfloat162 hb0 = hB[0], hb1 = hB[1], lb0 = lB[0], lb1 = lB[1];
            float b0 = __bfloat162float(hb0.x) + __bfloat162float(lb0.x);
            float b1 = __bfloat162float(hb0.y) + __bfloat162float(lb0.y);
            float b2 = __bfloat162float(hb1.x) + __bfloat162float(lb1.x);
            float b3 = __bfloat162float(hb1.y) + __bfloat162float(lb1.y);
            Bs[q * 2 + 0][r] = packf2(b0, b1);
            Bs[q * 2 + 1][r] = packf2(b2, b3);
        }
        __syncthreads();
#pragma unroll
        for (int kp = 0; kp < 16; kp++) {
            ulonglong2 aA = *(const ulonglong2*)&As[kp][ty * 4 + 0];
            ulonglong2 aB = *(const ulonglong2*)&As[kp][ty * 4 + 2];
            ulonglong2 bA = *(const ulonglong2*)&Bs[kp][tx * 4 + 0];
            ulonglong2 bB = *(const ulonglong2*)&Bs[kp][tx * 4 + 2];
            u64 a_[4] = {aA.x, aA.y, aB.x, aB.y};
            u64 b_[4] = {bA.x, bA.y, bB.x, bB.y};
#pragma unroll
            for (int i = 0; i < 4; i++)
#pragma unroll
                for (int j = 0; j < 4; j++)
                    acc[i][j] = ffma2(a_[i], b_[j], acc[i][j]);
        }
        __syncthreads();
    }

    float accf[4][4];
#pragma unroll
    for (int i = 0; i < 4; i++)
#pragma unroll
        for (int j = 0; j < 4; j++) {
            unsigned lo = (unsigned)acc[i][j];
            unsigned hi = (unsigned)(acc[i][j] >> 32);
            accf[i][j] = __uint_as_float(lo) + __uint_as_float(hi);
        }

#pragma unroll
    for (int i = 0; i < 4; i++)
#pragma unroll
        for (int j = 0; j < 4; j++)
            g_inner[(size_t)(rowBase + ty * 4 + i) * NR + colBase + tx * 4 + j] = accf[i][j];

    if (bx != by) {
        float (*Ct)[65] = (float (*)[65])smraw;
        __syncthreads();
#pragma unroll
        for (int i = 0; i < 4; i++)
#pragma unroll
            for (int j = 0; j < 4; j++)
                Ct[tx * 4 + j][ty * 4 + i] = accf[i][j];
        __syncthreads();
        for (int idx = tid; idx < 4096; idx += 256) {
            int rr = idx >> 6, cc = idx & 63;
            g_inner[(size_t)(colBase + rr) * NR + rowBase + cc] = Ct[rr][cc];
        }
    }
}

// ---------------- 3) fused per-row stats + loss (row cached in smem) ----------------
__global__ void __launch_bounds__(TPB) fused_kernel() {
    __shared__ float rowv[NR];               // 24 KB
    __shared__ unsigned char labs[NR];       // 6 KB
    __shared__ unsigned int hist[NBK];       // 8 KB
    __shared__ float simvals[256];
    __shared__ float bvals[512];
    __shared__ float redf[TPB];
    __shared__ int redi[TPB];
    __shared__ unsigned int partial[TPB];
    __shared__ unsigned int cumb[TPB];
    __shared__ unsigned int nsim_sh, nb_sh, cntabove_sh;
    __shared__ int bstar_sh;

    int row = blockIdx.x;
    int tid = threadIdx.x;
    size_t base = (size_t)row * NR;

    for (int i = tid; i < NR / 4; i += TPB) {
        float4 v = *(const float4*)&g_inner[base + (size_t)i * 4];
        *(float4*)&rowv[i * 4] = v;
        int4 lb = *(const int4*)&g_lab[i * 4];
        labs[i * 4 + 0] = (unsigned char)lb.x;
        labs[i * 4 + 1] = (unsigned char)lb.y;
        labs[i * 4 + 2] = (unsigned char)lb.z;
        labs[i * 4 + 3] = (unsigned char)lb.w;
    }
    for (int i = tid; i < NBK; i += TPB) hist[i] = 0u;
    if (tid == 0) { nsim_sh = 0u; nb_sh = 0u; bstar_sh = -1; cntabove_sh = 0u; }
    __syncthreads();

    unsigned char labr = labs[row];
    float sumS = 0.0f, sumDS = 0.0f;

    for (int col = tid; col < NR; col += TPB) {
        float v = rowv[col];
        if (labs[col] == labr) {
            unsigned int p = atomicAdd(&nsim_sh, 1u);
            if (p < 256u) simvals[p] = v;
            sumS += v;
        } else {
            sumDS += v;
            atomicAdd(&hist[bucket_of(v)], 1u);
        }
    }
    sumS = block_reduce_f(sumS, redf);
    sumDS = block_reduce_f(sumDS, redf);
    __syncthreads();

    int n_sim = (int)nsim_sh;
    int n_dis = NR - n_sim;
    int k = n_dis - (n_dis * 9) / 10;

    {
        const int BPT = NBK / TPB;
        int b0 = NBK - 1 - tid * BPT;
        unsigned int pc = 0u;
#pragma unroll
        for (int q = 0; q < BPT; q++) pc += hist[b0 - q];
        partial[tid] = pc;
        __syncthreads();
        if (tid == 0) {
            unsigned int c = 0u;
            for (int t = 0; t < TPB; t++) { cumb[t] = c; c += partial[t]; }
        }
        __syncthreads();
        if (n_dis > 0 && cumb[tid] < (unsigned)k && cumb[tid] + partial[tid] >= (unsigned)k) {
            unsigned int c = cumb[tid];
            for (int q = 0; q < BPT; q++) {
                int b = b0 - q;
                unsigned int h = hist[b];
                if (c + h >= (unsigned)k) { bstar_sh = b; cntabove_sh = c; break; }
                c += h;
            }
        }
        __syncthreads();
    }

    int bstar = bstar_sh;
    float sumAb = 0.0f;
    for (int col = tid; col < NR; col += TPB) {
        if (labs[col] != labr) {
            float v = rowv[col];
            int b = bucket_of(v);
            if (b > bstar) sumAb += v;
            else if (b == bstar) {
                unsigned int p = atomicAdd(&nb_sh, 1u);
                if (p < 512u) bvals[p] = v;
            }
        }
    }
    sumAb = block_reduce_f(sumAb, redf);
    __syncthreads();

    int cntb = (int)min(nb_sh, 512u);
    int r = k - (int)cntabove_sh;
    float topr = 0.0f;
    for (int i = tid; i < cntb; i += TPB) {
        float v = bvals[i];
        int rank = 0;
        for (int j = 0; j < cntb; j++) {
            float w = bvals[j];
            rank += (w > v) || (w == v && j < i);
        }
        if (rank < r) topr += v;
    }
    topr = block_reduce_f(topr, redf);

    int nsim_c = min(n_sim, 256);
    int m = n_sim - (n_sim * 9) / 10;
    float ssum = 0.0f;
    for (int i = tid; i < nsim_c; i += TPB) {
        float v = simvals[i];
        int rank = 0;
        for (int j = 0; j < nsim_c; j++) {
            float w = simvals[j];
            rank += (w < v) || (w == v && j < i);
        }
        if (rank < m) ssum += v;
    }
    ssum = block_reduce_f(ssum, redf);

    float fns = fmaxf((float)n_sim, 1.0f);
    float fnd = fmaxf((float)n_dis, 1.0f);
    float meanS  = fminf(fmaxf(sumS  / fns, 0.0f), UBF);
    float meanDS = fminf(fmaxf(sumDS / fnd, 0.0f), UBF);
    float dMax = 0.0f;
    if (n_dis > 0)
        dMax = fminf(fmaxf((sumAb + topr) / fmaxf((float)k, 1.0f), 0.0f), UBF);
    float sMin = fminf(fmaxf(ssum / fmaxf((float)m, 1.0f), 0.0f), UBF);
    float BP  = meanS  - (UBF - meanS) / UBF * fabsf(meanS - dMax);
    float BPd = meanDS + meanDS / UBF * fabsf(meanDS - sMin);

    float ps = 0.0f, ns = 0.0f;
    int pc = 0, nc = 0;
    for (int col = tid; col < NR; col += TPB) {
        float v = rowv[col];
        if (labs[col] == labr) {
            if (v != BP) {
                float dc = v - BP;
                float f = (v > BP) ? (CCOEF * dc) : (ACOEF * CCOEF * dc);
                ps += softplus_f(f);
                pc++;
            }
        } else {
            if (v != BPd) {
                float dcd = v - BPd;
                float f = (v < BPd) ? (CCOEF * dcd) : (ACOEF * CCOEF * dcd);
                ns += softplus_f(-f);
                nc++;
            }
        }
    }
    ps = block_reduce_f(ps, redf);
    ns = block_reduce_f(ns, redf);
    pc = block_reduce_i(pc, redi);
    nc = block_reduce_i(nc, redi);

    if (tid == 0) {
        int valid = (n_sim > 0 && n_dis > 0) ? 1 : 0;
        float rp = ps / fmaxf((float)pc, 1.0f);
        float rn = ns / fmaxf((float)nc, 1.0f);
        g_rowPos[row] = valid ? rp : 0.0f;
        g_rowNeg[row] = valid ? rn : 0.0f;
        g_valid[row] = valid;
    }
}

// ---------------- 4) final reduction (1024 threads, shuffle) ----------------
__global__ void __launch_bounds__(1024) final_kernel(float* __restrict__ out) {
    int tid = threadIdx.x;
    __shared__ float sp[32], sn[32], sq[32];
    __shared__ int sc[32];

    float p = 0.0f, n = 0.0f, q = 0.0f;
    int c = 0;
    for (int i = tid; i < NR; i += 1024) {
        p += g_rowPos[i];
        n += g_rowNeg[i];
        q += g_rowQ[i];
        c += g_valid[i];
    }
#pragma unroll
    for (int s = 16; s > 0; s >>= 1) {
        p += __shfl_down_sync(0xFFFFFFFFu, p, s);
        n += __shfl_down_sync(0xFFFFFFFFu, n, s);
        q += __shfl_down_sync(0xFFFFFFFFu, q, s);
        c += __shfl_down_sync(0xFFFFFFFFu, c, s);
    }
    int w = tid >> 5, l = tid & 31;
    if (l == 0) { sp[w] = p; sn[w] = n; sq[w] = q; sc[w] = c; }
    __syncthreads();
    if (w == 0) {
        p = sp[l]; n = sn[l]; q = sq[l]; c = sc[l];
#pragma unroll
        for (int s = 16; s > 0; s >>= 1) {
            p += __shfl_down_sync(0xFFFFFFFFu, p, s);
            n += __shfl_down_sync(0xFFFFFFFFu, n, s);
            q += __shfl_down_sync(0xFFFFFFFFu, q, s);
            c += __shfl_down_sync(0xFFFFFFFFu, c, s);
        }
        if (l == 0) {
            float cnt = (float)c;
            float posL = (c > 0) ? p / fmaxf(cnt, 1.0f) : 0.0f;
            float navL = (c > 0) ? n / fmaxf(cnt, 1.0f) : 0.0f;
            float qloss = ALPHAF * (q / (float)((size_t)NR * KB));
            out[0] = posL + navL + qloss;
        }
    }
}

// ---------------- launch ----------------
extern "C" void kernel_launch(void* const* d_in, const int* in_sizes, int n_in,
                              void* d_out, int out_size) {
    const float* u = (const float*)d_in[0];
    const int* y = (const int*)d_in[1];
    (void)in_sizes; (void)n_in; (void)out_size;
    float* out = (float*)d_out;

    cudaFuncSetAttribute(gemm_mma_kernel, cudaFuncAttributeMaxDynamicSharedMemorySize, MMA_SMEM);

    prep_kernel<<<NR, KB>>>(u, y);
    dim3 g(NR / GT, NR / GT);
    gemm_mma_kernel<<<g, 256, MMA_SMEM>>>();
    verify_kernel<<<1, 256>>>();
    dim3 gf(NR / 64, NR / 64);
    gemm_fb_kernel<<<gf, 256>>>();
    fused_kernel<<<NR, TPB>>>();
    final_kernel<<<1, 1024>>>(out);
}